// round 1
// baseline (speedup 1.0000x reference)
#include <cuda_runtime.h>

// SimpleMambaSSM: y = scan(exp(dt*A), dt*B*x, C) + x*D_skip
// Shapes: x (2,2048,1024), W_B/W_C (16,1024), W_dt (1024,1024), log_A (1024,16)

constexpr int Bsz  = 2;
constexpr int Lseq = 2048;
constexpr int Dm   = 1024;
constexpr int Ns   = 16;
constexpr int Mrows = Bsz * Lseq;   // 4096
constexpr int Kdim  = Dm;           // 1024

#define LOG2E 1.4426950408889634f

// Scratch (static __device__ — no allocation allowed)
__device__ float g_delta[Mrows * Dm];   // 16 MB
__device__ float g_bc[Mrows * 32];      // 512 KB: [m][0:16]=Bv, [m][16:32]=Cv

__device__ __forceinline__ float fast_exp2(float x) {
    float y;
    asm("ex2.approx.ftz.f32 %0, %1;" : "=f"(y) : "f"(x));
    return y;
}

// ---------------------------------------------------------------------------
// Kernel 1: delta = softplus(x @ W_dt^T + b_dt)   (NT SGEMM, 128x128x8 tiles)
// ---------------------------------------------------------------------------
__global__ void __launch_bounds__(256, 2) k_gemm_delta(
        const float* __restrict__ X,     // [Mrows, K]
        const float* __restrict__ W,     // [Dm, K] (row-major, K contiguous)
        const float* __restrict__ bias)  // [Dm]
{
    __shared__ float As[8][132];
    __shared__ float Bs[8][132];
    const int tid = threadIdx.x;
    const int lr  = tid >> 1;          // 0..127 tile row
    const int lk  = (tid & 1) * 4;     // 0 or 4
    const float* Ap = X + (blockIdx.y * 128 + lr) * Kdim + lk;
    const float* Bp = W + (blockIdx.x * 128 + lr) * Kdim + lk;
    const int tx = tid & 15;
    const int ty = tid >> 4;

    float acc[8][8];
    #pragma unroll
    for (int i = 0; i < 8; i++)
        #pragma unroll
        for (int j = 0; j < 8; j++) acc[i][j] = 0.f;

    for (int k0 = 0; k0 < Kdim; k0 += 8) {
        float4 a = *(const float4*)(Ap + k0);
        float4 b = *(const float4*)(Bp + k0);
        __syncthreads();
        As[lk + 0][lr] = a.x; As[lk + 1][lr] = a.y;
        As[lk + 2][lr] = a.z; As[lk + 3][lr] = a.w;
        Bs[lk + 0][lr] = b.x; Bs[lk + 1][lr] = b.y;
        Bs[lk + 2][lr] = b.z; Bs[lk + 3][lr] = b.w;
        __syncthreads();
        #pragma unroll
        for (int kk = 0; kk < 8; kk++) {
            float ar[8], br[8];
            #pragma unroll
            for (int i = 0; i < 8; i++) ar[i] = As[kk][ty * 8 + i];
            #pragma unroll
            for (int j = 0; j < 8; j++) br[j] = Bs[kk][tx * 8 + j];
            #pragma unroll
            for (int i = 0; i < 8; i++)
                #pragma unroll
                for (int j = 0; j < 8; j++)
                    acc[i][j] = fmaf(ar[i], br[j], acc[i][j]);
        }
    }

    const int row0 = blockIdx.y * 128 + ty * 8;
    const int col0 = blockIdx.x * 128 + tx * 8;
    #pragma unroll
    for (int i = 0; i < 8; i++) {
        #pragma unroll
        for (int j = 0; j < 8; j++) {
            float z = acc[i][j] + bias[col0 + j];
            float sp = (z > 20.f) ? z : log1pf(expf(z));   // softplus
            g_delta[(row0 + i) * Dm + col0 + j] = sp;
        }
    }
}

// ---------------------------------------------------------------------------
// Kernel 2: Bv/Cv = x @ [W_B;W_C]^T + bias   (skinny SGEMM, 64x32x32 tiles)
// g_bc[m][j], j<16 => Bv, j>=16 => Cv
// ---------------------------------------------------------------------------
__global__ void __launch_bounds__(256) k_gemm_bc(
        const float* __restrict__ X,
        const float* __restrict__ WB, const float* __restrict__ bB,
        const float* __restrict__ WC, const float* __restrict__ bC)
{
    __shared__ float xs[32][68];
    __shared__ float ws[32][36];
    const int tid = threadIdx.x;
    // x tile loaders: 64 rows x 8 float4 = 512 -> 2 per thread
    const int xr0 = tid >> 3;             // 0..31
    const int xk0 = (tid & 7) * 4;
    // W loaders: 32 rows x 8 float4 = 256 -> 1 per thread
    const int wr = tid >> 3;              // 0..31 (output index)
    const int wk = (tid & 7) * 4;
    const float* wrow = (wr < 16) ? (WB + wr * Kdim) : (WC + (wr - 16) * Kdim);

    const int tx = tid & 15;              // col pair
    const int ty = tid >> 4;              // row quad
    const int mbase = blockIdx.x * 64;

    float acc[4][2];
    #pragma unroll
    for (int i = 0; i < 4; i++) { acc[i][0] = 0.f; acc[i][1] = 0.f; }

    for (int k0 = 0; k0 < Kdim; k0 += 32) {
        float4 a0 = *(const float4*)(X + (mbase + xr0)      * Kdim + k0 + xk0);
        float4 a1 = *(const float4*)(X + (mbase + xr0 + 32) * Kdim + k0 + xk0);
        float4 w  = *(const float4*)(wrow + k0 + wk);
        __syncthreads();
        xs[xk0 + 0][xr0] = a0.x; xs[xk0 + 1][xr0] = a0.y;
        xs[xk0 + 2][xr0] = a0.z; xs[xk0 + 3][xr0] = a0.w;
        xs[xk0 + 0][xr0 + 32] = a1.x; xs[xk0 + 1][xr0 + 32] = a1.y;
        xs[xk0 + 2][xr0 + 32] = a1.z; xs[xk0 + 3][xr0 + 32] = a1.w;
        ws[wk + 0][wr] = w.x; ws[wk + 1][wr] = w.y;
        ws[wk + 2][wr] = w.z; ws[wk + 3][wr] = w.w;
        __syncthreads();
        #pragma unroll
        for (int kk = 0; kk < 32; kk++) {
            float ar[4];
            #pragma unroll
            for (int i = 0; i < 4; i++) ar[i] = xs[kk][ty * 4 + i];
            float b0 = ws[kk][tx * 2 + 0];
            float b1 = ws[kk][tx * 2 + 1];
            #pragma unroll
            for (int i = 0; i < 4; i++) {
                acc[i][0] = fmaf(ar[i], b0, acc[i][0]);
                acc[i][1] = fmaf(ar[i], b1, acc[i][1]);
            }
        }
    }

    #pragma unroll
    for (int i = 0; i < 4; i++) {
        #pragma unroll
        for (int j = 0; j < 2; j++) {
            int col = tx * 2 + j;
            float bias = (col < 16) ? bB[col] : bC[col - 16];
            g_bc[(mbase + ty * 4 + i) * 32 + col] = acc[i][j] + bias;
        }
    }
}

// ---------------------------------------------------------------------------
// Kernel 3: sequential scan over L.
// 16 lanes = 16 states of one (b,d) channel; 2 channels per warp.
// h[n]_{t} = exp(dt*A[n]) * h[n]_{t-1} + dt*Bv[n]*x ;  y = sum_n h[n]*Cv[n]
// Loads are double-buffered in batches of U=8 steps (independent of h chain).
// ---------------------------------------------------------------------------
__global__ void __launch_bounds__(256) k_scan(
        const float* __restrict__ X,
        const float* __restrict__ logA,     // [Dm, Ns]
        const float* __restrict__ Dskip,    // [Dm]
        float* __restrict__ out)
{
    const int tid  = threadIdx.x;
    const int lane = tid & 31;
    const int n    = lane & 15;
    const int half = lane >> 4;
    const int warp = tid >> 5;
    const int ch   = blockIdx.x * 16 + warp * 2 + half;  // 0..2047
    const int b    = ch >> 10;
    const int d    = ch & 1023;

    const float A2  = -expf(logA[d * Ns + n]) * LOG2E;   // A[d][n] * log2(e)
    const float dsk = Dskip[d];

    const float* xp  = X       + (b * Lseq) * Dm + d;
    const float* dp  = g_delta + (b * Lseq) * Dm + d;
    const float* bcp = g_bc    + (b * Lseq) * 32;
    float*       op  = out     + (b * Lseq) * Dm + d;

    float h = 0.f;
    constexpr int U = 8;
    float cd[U], cx[U], cB[U], cC[U];
    float nd[U], nx[U], nB[U], nC[U];

#define LOADB(pd, px, pB, pC, base)                          \
    _Pragma("unroll")                                        \
    for (int i = 0; i < U; i++) {                            \
        pd[i] = dp[(base + i) * Dm];                         \
        px[i] = xp[(base + i) * Dm];                         \
        pB[i] = bcp[(base + i) * 32 + n];                    \
        pC[i] = bcp[(base + i) * 32 + 16 + n];               \
    }

#define COMPB(pd, px, pB, pC, base)                          \
    _Pragma("unroll")                                        \
    for (int i = 0; i < U; i++) {                            \
        float dv = pd[i];                                    \
        float dA = fast_exp2(dv * A2);                       \
        h = fmaf(dA, h, dv * pB[i] * px[i]);                 \
        float p = h * pC[i];                                 \
        p += __shfl_xor_sync(0xffffffffu, p, 8);             \
        p += __shfl_xor_sync(0xffffffffu, p, 4);             \
        p += __shfl_xor_sync(0xffffffffu, p, 2);             \
        p += __shfl_xor_sync(0xffffffffu, p, 1);             \
        if (n == 0) op[(base + i) * Dm] = fmaf(px[i], dsk, p); \
    }

    LOADB(cd, cx, cB, cC, 0);
    for (int l0 = 0; l0 < Lseq; l0 += 2 * U) {
        LOADB(nd, nx, nB, nC, l0 + U);
        COMPB(cd, cx, cB, cC, l0);
        if (l0 + 2 * U < Lseq) { LOADB(cd, cx, cB, cC, l0 + 2 * U); }
        COMPB(nd, nx, nB, nC, l0 + U);
    }
#undef LOADB
#undef COMPB
}

// ---------------------------------------------------------------------------
extern "C" void kernel_launch(void* const* d_in, const int* in_sizes, int n_in,
                              void* d_out, int out_size)
{
    const float* x      = (const float*)d_in[0];
    const float* W_B    = (const float*)d_in[1];
    const float* b_B    = (const float*)d_in[2];
    const float* W_C    = (const float*)d_in[3];
    const float* b_C    = (const float*)d_in[4];
    const float* W_dt   = (const float*)d_in[5];
    const float* b_dt   = (const float*)d_in[6];
    const float* log_A  = (const float*)d_in[7];
    const float* D_skip = (const float*)d_in[8];
    float* out = (float*)d_out;

    dim3 g1(Dm / 128, Mrows / 128);            // (8, 32)
    k_gemm_delta<<<g1, 256>>>(x, W_dt, b_dt);
    k_gemm_bc<<<Mrows / 64, 256>>>(x, W_B, b_B, W_C, b_C);
    k_scan<<<(Bsz * Dm) / 16, 256>>>(x, log_A, D_skip, out);
}

// round 3
// speedup vs baseline: 1.3403x; 1.3403x over previous
#include <cuda_runtime.h>
#include <cuda_bf16.h>
#include <cstdint>

// SimpleMambaSSM on sm_100 (base target — no tcgen05!):
//  - delta GEMM via mma.sync bf16 3-pass hi/lo split (fp32-accurate)
//  - transposed scan layout, x-transpose fused into the B/C projection kernel
// Shapes: x (2,2048,1024), W_B/W_C (16,1024), W_dt (1024,1024), log_A (1024,16)

constexpr int Bsz  = 2;
constexpr int Lseq = 2048;
constexpr int Dm   = 1024;
constexpr int Ns   = 16;
constexpr int Mrows = Bsz * Lseq;   // 4096
constexpr int Kdim  = Dm;           // 1024

#define LOG2E 1.4426950408889634f

// ---------------- scratch (static __device__, no allocation) ---------------
__device__ float g_dT[Dm * Mrows];       // delta^T: [d][b*L + l]   16MB
__device__ float g_xT[Dm * Mrows];       // x^T:     [d][b*L + l]   16MB
__device__ float g_yT[Bsz * Dm * Lseq];  // y^T:     [ch][l]        16MB
__device__ float g_bc[Mrows * 32];       // [m][0:16]=Bv,[16:32]=Cv 512KB

__device__ __forceinline__ float fast_exp2(float x) {
    float y;
    asm("ex2.approx.ftz.f32 %0, %1;" : "=f"(y) : "f"(x));
    return y;
}
__device__ __forceinline__ float softplus_f(float z) {
    return (z > 20.f) ? z : log1pf(expf(z));
}

// fp32 -> (hi bf16 pair via truncation, lo bf16 pair of exact residual)
__device__ __forceinline__ void cvt_pair(float x0, float x1,
                                         uint32_t& hi, uint32_t& lo) {
    uint32_t u0 = __float_as_uint(x0), u1 = __float_as_uint(x1);
    hi = __byte_perm(u0, u1, 0x7632);
    float l0 = x0 - __uint_as_float(u0 & 0xFFFF0000u);
    float l1 = x1 - __uint_as_float(u1 & 0xFFFF0000u);
    __nv_bfloat162 t = __floats2bfloat162_rn(l0, l1);
    lo = *reinterpret_cast<uint32_t*>(&t);
}

__device__ __forceinline__ void mma16816(float* c, const uint32_t* a,
                                         const uint32_t* b) {
    asm volatile(
        "mma.sync.aligned.m16n8k16.row.col.f32.bf16.bf16.f32 "
        "{%0,%1,%2,%3}, {%4,%5,%6,%7}, {%8,%9}, {%0,%1,%2,%3};"
        : "+f"(c[0]), "+f"(c[1]), "+f"(c[2]), "+f"(c[3])
        : "r"(a[0]), "r"(a[1]), "r"(a[2]), "r"(a[3]), "r"(b[0]), "r"(b[1]));
}

// ---------------------------------------------------------------------------
// Kernel 1: delta = softplus(x @ W_dt^T + b_dt), written transposed to g_dT.
// CTA 128(m) x 128(n), warp 64x32, K-chunk 32 (2 ksteps of 16), 2-stage smem.
// Operand smem rows padded to 80B (20 words) -> conflict-free fragment LDS.
// ---------------------------------------------------------------------------
constexpr int PAW = 20;                      // words per operand row (80B)
constexpr int MATW = 128 * PAW;              // 2560 words per matrix
constexpr int STAGEW = 4 * MATW;             // Ahi Alo Bhi Blo = 10240 words
constexpr int SMEM_DELTA = 2 * STAGEW * 4;   // 81920 bytes

__global__ void __launch_bounds__(256, 1) k_delta_mma(
        const float* __restrict__ X, const float* __restrict__ W,
        const float* __restrict__ bias)
{
    extern __shared__ uint32_t smw[];
    const int tid  = threadIdx.x;
    const int wid  = tid >> 5;
    const int lane = tid & 31;
    const int wm = wid & 1;          // warp m (2 x 64 rows)
    const int wn = wid >> 1;         // warp n (4 x 32 cols)
    const int g  = lane >> 2;        // group id 0..7
    const int tg = lane & 3;         // thread-in-group
    const int m0 = blockIdx.y * 128;
    const int n0 = blockIdx.x * 128;

    // loaders: each thread handles 16 floats of A and 16 of B per chunk
    const int lrow = tid >> 1;               // 0..127
    const int lcg  = (tid & 1) * 16;         // col group
    const float4* Ap = (const float4*)(X + (size_t)(m0 + lrow) * Kdim + lcg);
    const float4* Bp = (const float4*)(W + (size_t)(n0 + lrow) * Kdim + lcg);

    float acc[4][4][4];
    #pragma unroll
    for (int mt = 0; mt < 4; mt++)
        #pragma unroll
        for (int nt = 0; nt < 4; nt++)
            #pragma unroll
            for (int j = 0; j < 4; j++) acc[mt][nt][j] = 0.f;

    float4 abuf[4], bbuf[4];
    #pragma unroll
    for (int q = 0; q < 4; q++) { abuf[q] = Ap[q]; bbuf[q] = Bp[q]; }

    // STS helper offsets (in words)
    const int stw = lrow * PAW + (tid & 1) * 8;

    #pragma unroll 1
    for (int c = 0; c < 32; c++) {
        const int s = c & 1;
        uint32_t* Ah = smw + s * STAGEW;
        uint32_t* Al = Ah + MATW;
        uint32_t* Bh = Ah + 2 * MATW;
        uint32_t* Bl = Ah + 3 * MATW;

        // ---- convert + STS current chunk ----
        {
            uint32_t ah[8], al[8], bh[8], bl[8];
            #pragma unroll
            for (int q = 0; q < 4; q++) {
                cvt_pair(abuf[q].x, abuf[q].y, ah[q*2],   al[q*2]);
                cvt_pair(abuf[q].z, abuf[q].w, ah[q*2+1], al[q*2+1]);
                cvt_pair(bbuf[q].x, bbuf[q].y, bh[q*2],   bl[q*2]);
                cvt_pair(bbuf[q].z, bbuf[q].w, bh[q*2+1], bl[q*2+1]);
            }
            *(uint4*)(Ah + stw)     = make_uint4(ah[0], ah[1], ah[2], ah[3]);
            *(uint4*)(Ah + stw + 4) = make_uint4(ah[4], ah[5], ah[6], ah[7]);
            *(uint4*)(Al + stw)     = make_uint4(al[0], al[1], al[2], al[3]);
            *(uint4*)(Al + stw + 4) = make_uint4(al[4], al[5], al[6], al[7]);
            *(uint4*)(Bh + stw)     = make_uint4(bh[0], bh[1], bh[2], bh[3]);
            *(uint4*)(Bh + stw + 4) = make_uint4(bh[4], bh[5], bh[6], bh[7]);
            *(uint4*)(Bl + stw)     = make_uint4(bl[0], bl[1], bl[2], bl[3]);
            *(uint4*)(Bl + stw + 4) = make_uint4(bl[4], bl[5], bl[6], bl[7]);
        }
        __syncthreads();

        // ---- prefetch next chunk ----
        if (c + 1 < 32) {
            const float4* An = Ap + (c + 1) * 8;
            const float4* Bn = Bp + (c + 1) * 8;
            #pragma unroll
            for (int q = 0; q < 4; q++) { abuf[q] = An[q]; bbuf[q] = Bn[q]; }
        }

        // ---- compute on this stage: 2 ksteps x 16 tiles x 3 passes ----
        #pragma unroll
        for (int ks = 0; ks < 2; ks++) {
            uint32_t ahf[4][4], alf[4][4], bhf[4][2], blf[4][2];
            #pragma unroll
            for (int mt = 0; mt < 4; mt++) {
                const int r = wm * 64 + mt * 16 + g;
                const int base = r * PAW + ks * 8 + tg;
                ahf[mt][0] = Ah[base];
                ahf[mt][1] = Ah[base + 8 * PAW];
                ahf[mt][2] = Ah[base + 4];
                ahf[mt][3] = Ah[base + 8 * PAW + 4];
                alf[mt][0] = Al[base];
                alf[mt][1] = Al[base + 8 * PAW];
                alf[mt][2] = Al[base + 4];
                alf[mt][3] = Al[base + 8 * PAW + 4];
            }
            #pragma unroll
            for (int nt = 0; nt < 4; nt++) {
                const int n = wn * 32 + nt * 8 + g;
                const int base = n * PAW + ks * 8 + tg;
                bhf[nt][0] = Bh[base];
                bhf[nt][1] = Bh[base + 4];
                blf[nt][0] = Bl[base];
                blf[nt][1] = Bl[base + 4];
            }
            #pragma unroll
            for (int mt = 0; mt < 4; mt++)
                #pragma unroll
                for (int nt = 0; nt < 4; nt++) {
                    mma16816(acc[mt][nt], ahf[mt], bhf[nt]);
                    mma16816(acc[mt][nt], ahf[mt], blf[nt]);
                    mma16816(acc[mt][nt], alf[mt], bhf[nt]);
                }
        }
        __syncthreads();
    }

    // ---- epilogue: bias + softplus, transpose via smem, write g_dT -------
    float* st = (float*)smw;                 // [32][132] floats, reused
    #pragma unroll 1
    for (int s = 0; s < 4; s++) {
        if (wn == s) {
            #pragma unroll
            for (int nt = 0; nt < 4; nt++) {
                const int dl = nt * 8 + tg * 2;
                const float b0v = bias[n0 + s * 32 + dl];
                const float b1v = bias[n0 + s * 32 + dl + 1];
                #pragma unroll
                for (int mt = 0; mt < 4; mt++) {
                    const int ml = wm * 64 + mt * 16 + g;
                    st[dl * 132 + ml]           = softplus_f(acc[mt][nt][0] + b0v);
                    st[(dl + 1) * 132 + ml]     = softplus_f(acc[mt][nt][1] + b1v);
                    st[dl * 132 + ml + 8]       = softplus_f(acc[mt][nt][2] + b0v);
                    st[(dl + 1) * 132 + ml + 8] = softplus_f(acc[mt][nt][3] + b1v);
                }
            }
        }
        __syncthreads();
        {
            const int dl = tid >> 3;
            const int mg = (tid & 7) * 16;
            float* dst = g_dT + (size_t)(n0 + s * 32 + dl) * Mrows + m0 + mg;
            #pragma unroll
            for (int i = 0; i < 4; i++)
                ((float4*)dst)[i] = *(float4*)&st[dl * 132 + mg + i * 4];
        }
        __syncthreads();
    }
}

// ---------------------------------------------------------------------------
// Kernel 2: Bv/Cv = x @ [W_B;W_C]^T + bias, AND writes x^T to g_xT
// (the smem x tile xs[k][m] is already the transposed tile — free transpose)
// ---------------------------------------------------------------------------
__global__ void __launch_bounds__(256) k_gemm_bc(
        const float* __restrict__ X,
        const float* __restrict__ WB, const float* __restrict__ bB,
        const float* __restrict__ WC, const float* __restrict__ bC)
{
    __shared__ float xs[32][72];   // pitch 72 words (288B, 16B-aligned rows)
    __shared__ float ws[32][36];
    const int tid = threadIdx.x;
    const int xr0 = tid >> 3;
    const int xk0 = (tid & 7) * 4;
    const int wr = tid >> 3;
    const int wk = (tid & 7) * 4;
    const float* wrow = (wr < 16) ? (WB + wr * Kdim) : (WC + (wr - 16) * Kdim);

    const int tx = tid & 15;
    const int ty = tid >> 4;
    const int mbase = blockIdx.x * 64;

    float acc[4][2];
    #pragma unroll
    for (int i = 0; i < 4; i++) { acc[i][0] = 0.f; acc[i][1] = 0.f; }

    for (int k0 = 0; k0 < Kdim; k0 += 32) {
        float4 a0 = *(const float4*)(X + (size_t)(mbase + xr0)      * Kdim + k0 + xk0);
        float4 a1 = *(const float4*)(X + (size_t)(mbase + xr0 + 32) * Kdim + k0 + xk0);
        float4 w  = *(const float4*)(wrow + k0 + wk);
        __syncthreads();
        xs[xk0 + 0][xr0] = a0.x; xs[xk0 + 1][xr0] = a0.y;
        xs[xk0 + 2][xr0] = a0.z; xs[xk0 + 3][xr0] = a0.w;
        xs[xk0 + 0][xr0 + 32] = a1.x; xs[xk0 + 1][xr0 + 32] = a1.y;
        xs[xk0 + 2][xr0 + 32] = a1.z; xs[xk0 + 3][xr0 + 32] = a1.w;
        ws[wk + 0][wr] = w.x; ws[wk + 1][wr] = w.y;
        ws[wk + 2][wr] = w.z; ws[wk + 3][wr] = w.w;
        __syncthreads();
        #pragma unroll
        for (int kk = 0; kk < 32; kk++) {
            float ar[4];
            #pragma unroll
            for (int i = 0; i < 4; i++) ar[i] = xs[kk][ty * 4 + i];
            float b0 = ws[kk][tx * 2 + 0];
            float b1 = ws[kk][tx * 2 + 1];
            #pragma unroll
            for (int i = 0; i < 4; i++) {
                acc[i][0] = fmaf(ar[i], b0, acc[i][0]);
                acc[i][1] = fmaf(ar[i], b1, acc[i][1]);
            }
        }
        // write transposed x tile: g_xT[k0+kk][mbase + m]
        {
            const int kk = tid >> 3;
            const int mq = (tid & 7) * 8;
            float* dst = g_xT + (size_t)(k0 + kk) * Mrows + mbase + mq;
            ((float4*)dst)[0] = *(float4*)&xs[kk][mq];
            ((float4*)dst)[1] = *(float4*)&xs[kk][mq + 4];
        }
    }
    #pragma unroll
    for (int i = 0; i < 4; i++) {
        #pragma unroll
        for (int j = 0; j < 2; j++) {
            int col = tx * 2 + j;
            float bias = (col < 16) ? bB[col] : bC[col - 16];
            g_bc[(mbase + ty * 4 + i) * 32 + col] = acc[i][j] + bias;
        }
    }
}

// ---------------------------------------------------------------------------
// Kernel 3: scan. 16 lanes = 16 states of one channel; 2 channels per warp.
// Reads g_dT/g_xT contiguously (float4 per 4 steps); bc staged via smem.
// ---------------------------------------------------------------------------
__global__ void __launch_bounds__(256) k_scan2(const float* __restrict__ logA)
{
    __shared__ float bs[2][16 * 32];
    const int tid  = threadIdx.x;
    const int lane = tid & 31;
    const int n    = lane & 15;
    const int half = lane >> 4;
    const int warp = tid >> 5;
    const int ch   = blockIdx.x * 16 + warp * 2 + half;   // 0..2047
    const int b    = ch >> 10;
    const int d    = ch & 1023;

    const float A2 = -expf(logA[d * Ns + n]) * LOG2E;

    const float4* dT = (const float4*)(g_dT + (size_t)d * Mrows + b * Lseq);
    const float4* xT = (const float4*)(g_xT + (size_t)d * Mrows + b * Lseq);
    float* yp = g_yT + (size_t)ch * Lseq;
    const float* bcsrc = g_bc + (size_t)(b * Lseq) * 32;

    bs[0][tid]       = bcsrc[tid];
    bs[0][tid + 256] = bcsrc[tid + 256];
    __syncthreads();

    float h = 0.f;
    #pragma unroll 1
    for (int l0 = 0; l0 < Lseq; l0 += 16) {
        const int p = (l0 >> 4) & 1;
        float nb0 = 0.f, nb1 = 0.f;
        const bool more = (l0 + 16 < Lseq);
        if (more) {
            nb0 = bcsrc[(l0 + 16) * 32 + tid];
            nb1 = bcsrc[(l0 + 16) * 32 + tid + 256];
        }
        float4 dv4[4], xv4[4];
        #pragma unroll
        for (int gq = 0; gq < 4; gq++) {
            dv4[gq] = dT[(l0 >> 2) + gq];
            xv4[gq] = xT[(l0 >> 2) + gq];
        }
        #pragma unroll
        for (int gq = 0; gq < 4; gq++) {
            float dvs[4] = {dv4[gq].x, dv4[gq].y, dv4[gq].z, dv4[gq].w};
            float xvs[4] = {xv4[gq].x, xv4[gq].y, xv4[gq].z, xv4[gq].w};
            float y[4];
            #pragma unroll
            for (int i = 0; i < 4; i++) {
                const int st = gq * 4 + i;
                float dA  = fast_exp2(dvs[i] * A2);
                float dBx = dvs[i] * xvs[i] * bs[p][st * 32 + n];
                h = fmaf(dA, h, dBx);
                float pr = h * bs[p][st * 32 + 16 + n];
                pr += __shfl_xor_sync(0xffffffffu, pr, 8);
                pr += __shfl_xor_sync(0xffffffffu, pr, 4);
                pr += __shfl_xor_sync(0xffffffffu, pr, 2);
                pr += __shfl_xor_sync(0xffffffffu, pr, 1);
                y[i] = pr;
            }
            if (n == 0)
                *(float4*)(yp + l0 + gq * 4) = make_float4(y[0], y[1], y[2], y[3]);
        }
        if (more) {
            bs[p ^ 1][tid]       = nb0;
            bs[p ^ 1][tid + 256] = nb1;
        }
        __syncthreads();
    }
}

// ---------------------------------------------------------------------------
// Kernel 4: finalize. out[b,l,d] = yT[ch][l] + x*Dskip (32x32 smem transpose)
// ---------------------------------------------------------------------------
__global__ void __launch_bounds__(256) k_finalize(
        const float* __restrict__ X, const float* __restrict__ Dskip,
        float* __restrict__ out)
{
    __shared__ float t[32][33];
    const int l0 = blockIdx.x * 32;
    const int d0 = blockIdx.y * 32;
    const int b  = blockIdx.z;
    const int tx = threadIdx.x;
    const int ty = threadIdx.y;
    #pragma unroll
    for (int i = 0; i < 4; i++) {
        int d = d0 + ty + i * 8;
        t[ty + i * 8][tx] = g_yT[(size_t)(b * Dm + d) * Lseq + l0 + tx];
    }
    __syncthreads();
    const float dsk = Dskip[d0 + tx];
    #pragma unroll
    for (int i = 0; i < 4; i++) {
        int l = l0 + ty + i * 8;
        size_t idx = (size_t)(b * Lseq + l) * Dm + d0 + tx;
        out[idx] = fmaf(X[idx], dsk, t[tx][ty + i * 8]);
    }
}

// ---------------------------------------------------------------------------
extern "C" void kernel_launch(void* const* d_in, const int* in_sizes, int n_in,
                              void* d_out, int out_size)
{
    const float* x      = (const float*)d_in[0];
    const float* W_B    = (const float*)d_in[1];
    const float* b_B    = (const float*)d_in[2];
    const float* W_C    = (const float*)d_in[3];
    const float* b_C    = (const float*)d_in[4];
    const float* W_dt   = (const float*)d_in[5];
    const float* b_dt   = (const float*)d_in[6];
    const float* log_A  = (const float*)d_in[7];
    const float* D_skip = (const float*)d_in[8];
    float* out = (float*)d_out;

    cudaFuncSetAttribute(k_delta_mma,
        cudaFuncAttributeMaxDynamicSharedMemorySize, SMEM_DELTA);

    dim3 g1(Dm / 128, Mrows / 128);                 // (8, 32)
    k_delta_mma<<<g1, 256, SMEM_DELTA>>>(x, W_dt, b_dt);
    k_gemm_bc<<<Mrows / 64, 256>>>(x, W_B, b_B, W_C, b_C);
    k_scan2<<<(Bsz * Dm) / 16, 256>>>(log_A);
    dim3 g4(Lseq / 32, Dm / 32, Bsz);
    k_finalize<<<g4, dim3(32, 8)>>>(x, D_skip, out);
}

// round 4
// speedup vs baseline: 1.3859x; 1.0340x over previous
#include <cuda_runtime.h>
#include <cuda_bf16.h>
#include <cstdint>

// SimpleMambaSSM on sm_100 (base target — no tcgen05):
//  - prep kernel: fp32 -> bf16 hi/lo arrays for X and W_dt
//  - delta GEMM: cp.async 3-stage + ldmatrix + mma.sync bf16 3-pass split
//  - transposed scan layout; x^T fused into B/C projection kernel
// Shapes: x (2,2048,1024), W_B/W_C (16,1024), W_dt (1024,1024), log_A (1024,16)

constexpr int Bsz  = 2;
constexpr int Lseq = 2048;
constexpr int Dm   = 1024;
constexpr int Ns   = 16;
constexpr int Mrows = Bsz * Lseq;   // 4096
constexpr int Kdim  = Dm;           // 1024

#define LOG2E 1.4426950408889634f

// ---------------- scratch (static __device__, no allocation) ---------------
__device__ float g_dT[Dm * Mrows];       // delta^T: [d][b*L + l]   16MB
__device__ float g_xT[Dm * Mrows];       // x^T:     [d][b*L + l]   16MB
__device__ float g_yT[Bsz * Dm * Lseq];  // y^T:     [ch][l]        16MB
__device__ float g_bc[Mrows * 32];       // [m][0:16]=Bv,[16:32]=Cv 512KB
__device__ __nv_bfloat16 g_Ahi[Mrows * Kdim];  // x hi   8MB
__device__ __nv_bfloat16 g_Alo[Mrows * Kdim];  // x lo   8MB
__device__ __nv_bfloat16 g_Bhi[Dm * Kdim];     // W hi   2MB
__device__ __nv_bfloat16 g_Blo[Dm * Kdim];     // W lo   2MB

__device__ __forceinline__ float fast_exp2(float x) {
    float y;
    asm("ex2.approx.ftz.f32 %0, %1;" : "=f"(y) : "f"(x));
    return y;
}
__device__ __forceinline__ float softplus_f(float z) {
    return (z > 20.f) ? z : log1pf(expf(z));
}
__device__ __forceinline__ uint32_t smem_u32(const void* p) {
    uint32_t a;
    asm("{ .reg .u64 t; cvta.to.shared.u64 t, %1; cvt.u32.u64 %0, t; }"
        : "=r"(a) : "l"(p));
    return a;
}
// fp32 pair -> (hi bf16 pair via truncation, lo bf16 pair of residual)
__device__ __forceinline__ void cvt_pair(float x0, float x1,
                                         uint32_t& hi, uint32_t& lo) {
    uint32_t u0 = __float_as_uint(x0), u1 = __float_as_uint(x1);
    hi = __byte_perm(u0, u1, 0x7632);
    float l0 = x0 - __uint_as_float(u0 & 0xFFFF0000u);
    float l1 = x1 - __uint_as_float(u1 & 0xFFFF0000u);
    __nv_bfloat162 t = __floats2bfloat162_rn(l0, l1);
    lo = *reinterpret_cast<uint32_t*>(&t);
}
__device__ __forceinline__ void mma16816(float* c, const uint32_t* a,
                                         const uint32_t* b) {
    asm volatile(
        "mma.sync.aligned.m16n8k16.row.col.f32.bf16.bf16.f32 "
        "{%0,%1,%2,%3}, {%4,%5,%6,%7}, {%8,%9}, {%0,%1,%2,%3};"
        : "+f"(c[0]), "+f"(c[1]), "+f"(c[2]), "+f"(c[3])
        : "r"(a[0]), "r"(a[1]), "r"(a[2]), "r"(a[3]), "r"(b[0]), "r"(b[1]));
}
__device__ __forceinline__ void ldsm4(uint32_t* r, uint32_t addr) {
    asm volatile("ldmatrix.sync.aligned.m8n8.x4.shared.b16 {%0,%1,%2,%3}, [%4];"
        : "=r"(r[0]), "=r"(r[1]), "=r"(r[2]), "=r"(r[3]) : "r"(addr));
}
__device__ __forceinline__ void cp16(uint32_t dst, const void* src) {
    asm volatile("cp.async.cg.shared.global [%0], [%1], 16;"
        :: "r"(dst), "l"(src) : "memory");
}

// ---------------------------------------------------------------------------
// Kernel 0: convert X and W_dt to bf16 hi/lo. Block handles 2048 elems.
// Blocks [0,2048): X;  [2048,2560): W.
// ---------------------------------------------------------------------------
__global__ void __launch_bounds__(256) k_convert(
        const float* __restrict__ X, const float* __restrict__ W)
{
    const int bid = blockIdx.x;
    const float* src;
    __nv_bfloat16 *hi, *lo;
    size_t base;
    if (bid < 2048) { src = X; hi = g_Ahi; lo = g_Alo; base = (size_t)bid * 2048; }
    else { src = W; hi = g_Bhi; lo = g_Blo; base = (size_t)(bid - 2048) * 2048; }
    const size_t i0 = base + (size_t)threadIdx.x * 8;
    float4 v0 = *(const float4*)(src + i0);
    float4 v1 = *(const float4*)(src + i0 + 4);
    uint32_t h[4], l[4];
    cvt_pair(v0.x, v0.y, h[0], l[0]);
    cvt_pair(v0.z, v0.w, h[1], l[1]);
    cvt_pair(v1.x, v1.y, h[2], l[2]);
    cvt_pair(v1.z, v1.w, h[3], l[3]);
    *(uint4*)(hi + i0) = make_uint4(h[0], h[1], h[2], h[3]);
    *(uint4*)(lo + i0) = make_uint4(l[0], l[1], l[2], l[3]);
}

// ---------------------------------------------------------------------------
// Kernel 1: delta = softplus(x @ W_dt^T + b_dt) -> g_dT (transposed)
// CTA 128x128, warp 64x32, K-chunk 64 bf16, 3-stage cp.async, ldmatrix frags.
// Stage layout: Ahi[16KB] Alo[16KB] Bhi[16KB] Blo[16KB]; SW128 XOR swizzle.
// ---------------------------------------------------------------------------
constexpr int STAGE_B = 65536;
constexpr int SMEM_GEMM = 3 * STAGE_B;   // 196608

__global__ void __launch_bounds__(256, 1) k_delta_mma(
        const float* __restrict__ bias)
{
    extern __shared__ char smem[];
    const uint32_t sb = smem_u32(smem);
    const int tid  = threadIdx.x;
    const int wid  = tid >> 5;
    const int lane = tid & 31;
    const int wm = wid & 1;
    const int wn = wid >> 1;
    const int g  = lane >> 2;
    const int tg = lane & 3;
    const int m0 = blockIdx.y * 128;
    const int n0 = blockIdx.x * 128;

    // cp.async loader mapping: row = tid>>1 (0..127), 4 16B-chunks each
    const int lrow = tid >> 1;
    const int lc0  = (tid & 1) * 4;
    const __nv_bfloat16* gAh = g_Ahi + (size_t)(m0 + lrow) * Kdim;
    const __nv_bfloat16* gAl = g_Alo + (size_t)(m0 + lrow) * Kdim;
    const __nv_bfloat16* gBh = g_Bhi + (size_t)(n0 + lrow) * Kdim;
    const __nv_bfloat16* gBl = g_Blo + (size_t)(n0 + lrow) * Kdim;
    const uint32_t swbase = sb + (uint32_t)lrow * 128;
    const int rx = lrow & 7;

    // ldmatrix per-lane address components
    const uint32_t a_row = (uint32_t)(wm * 64 + (lane & 15));
    const uint32_t a_chi = (uint32_t)(lane >> 4);
    const uint32_t axor  = (uint32_t)(lane & 7);
    const uint32_t b_row = (uint32_t)(wn * 32 + ((lane >> 4) & 1) * 8 + (lane & 7));
    const uint32_t b_chi = (uint32_t)((lane >> 3) & 1);

    float acc[4][4][4];
    #pragma unroll
    for (int mt = 0; mt < 4; mt++)
        #pragma unroll
        for (int nt = 0; nt < 4; nt++)
            #pragma unroll
            for (int j = 0; j < 4; j++) acc[mt][nt][j] = 0.f;

    auto issue = [&](int c) {
        const uint32_t st = swbase + (uint32_t)(c % 3) * STAGE_B;
        const int kb = c * 64;
        #pragma unroll
        for (int i = 0; i < 4; i++) {
            const int cc = lc0 + i;
            const uint32_t sw = (uint32_t)((cc ^ rx) * 16);
            const int go = kb + cc * 8;
            cp16(st + sw,                 gAh + go);
            cp16(st + sw + 16384,         gAl + go);
            cp16(st + sw + 32768,         gBh + go);
            cp16(st + sw + 49152,         gBl + go);
        }
        asm volatile("cp.async.commit_group;" ::: "memory");
    };

    issue(0);
    issue(1);

    #pragma unroll 1
    for (int c = 0; c < 16; c++) {
        if (c + 2 < 16) issue(c + 2);
        else asm volatile("cp.async.commit_group;" ::: "memory");
        asm volatile("cp.async.wait_group 2;" ::: "memory");
        __syncthreads();

        const uint32_t st = sb + (uint32_t)(c % 3) * STAGE_B;
        #pragma unroll
        for (int ks = 0; ks < 4; ks++) {
            uint32_t bh[8], bl[8];
            #pragma unroll
            for (int bt = 0; bt < 2; bt++) {
                const uint32_t addr = st + 32768 +
                    (b_row + (uint32_t)bt * 16) * 128 +
                    (((uint32_t)(ks * 2) + b_chi) ^ axor) * 16;
                ldsm4(bh + bt * 4, addr);
                ldsm4(bl + bt * 4, addr + 16384);
            }
            #pragma unroll
            for (int mt = 0; mt < 4; mt++) {
                const uint32_t addr = st +
                    (a_row + (uint32_t)mt * 16) * 128 +
                    (((uint32_t)(ks * 2) + a_chi) ^ axor) * 16;
                uint32_t ah[4], al[4];
                ldsm4(ah, addr);
                ldsm4(al, addr + 16384);
                #pragma unroll
                for (int nt = 0; nt < 4; nt++) {
                    mma16816(acc[mt][nt], ah, bh + nt * 2);
                    mma16816(acc[mt][nt], ah, bl + nt * 2);
                    mma16816(acc[mt][nt], al, bh + nt * 2);
                }
            }
        }
        __syncthreads();
    }
    asm volatile("cp.async.wait_group 0;" ::: "memory");
    __syncthreads();

    // ---- epilogue: bias + softplus, transpose via smem, write g_dT -------
    float* st = (float*)smem;                // [32][132] floats
    #pragma unroll 1
    for (int s = 0; s < 4; s++) {
        if (wn == s) {
            #pragma unroll
            for (int nt = 0; nt < 4; nt++) {
                const int dl = nt * 8 + tg * 2;
                const float b0v = bias[n0 + s * 32 + dl];
                const float b1v = bias[n0 + s * 32 + dl + 1];
                #pragma unroll
                for (int mt = 0; mt < 4; mt++) {
                    const int ml = wm * 64 + mt * 16 + g;
                    st[dl * 132 + ml]           = softplus_f(acc[mt][nt][0] + b0v);
                    st[(dl + 1) * 132 + ml]     = softplus_f(acc[mt][nt][1] + b1v);
                    st[dl * 132 + ml + 8]       = softplus_f(acc[mt][nt][2] + b0v);
                    st[(dl + 1) * 132 + ml + 8] = softplus_f(acc[mt][nt][3] + b1v);
                }
            }
        }
        __syncthreads();
        {
            const int dl = tid >> 3;
            const int mg = (tid & 7) * 16;
            float* dst = g_dT + (size_t)(n0 + s * 32 + dl) * Mrows + m0 + mg;
            #pragma unroll
            for (int i = 0; i < 4; i++)
                ((float4*)dst)[i] = *(float4*)&st[dl * 132 + mg + i * 4];
        }
        __syncthreads();
    }
}

// ---------------------------------------------------------------------------
// Kernel 2: Bv/Cv = x @ [W_B;W_C]^T + bias, AND writes x^T to g_xT
// ---------------------------------------------------------------------------
__global__ void __launch_bounds__(256) k_gemm_bc(
        const float* __restrict__ X,
        const float* __restrict__ WB, const float* __restrict__ bB,
        const float* __restrict__ WC, const float* __restrict__ bC)
{
    __shared__ float xs[32][72];
    __shared__ float ws[32][36];
    const int tid = threadIdx.x;
    const int xr0 = tid >> 3;
    const int xk0 = (tid & 7) * 4;
    const int wr = tid >> 3;
    const int wk = (tid & 7) * 4;
    const float* wrow = (wr < 16) ? (WB + wr * Kdim) : (WC + (wr - 16) * Kdim);

    const int tx = tid & 15;
    const int ty = tid >> 4;
    const int mbase = blockIdx.x * 64;

    float acc[4][2];
    #pragma unroll
    for (int i = 0; i < 4; i++) { acc[i][0] = 0.f; acc[i][1] = 0.f; }

    for (int k0 = 0; k0 < Kdim; k0 += 32) {
        float4 a0 = *(const float4*)(X + (size_t)(mbase + xr0)      * Kdim + k0 + xk0);
        float4 a1 = *(const float4*)(X + (size_t)(mbase + xr0 + 32) * Kdim + k0 + xk0);
        float4 w  = *(const float4*)(wrow + k0 + wk);
        __syncthreads();
        xs[xk0 + 0][xr0] = a0.x; xs[xk0 + 1][xr0] = a0.y;
        xs[xk0 + 2][xr0] = a0.z; xs[xk0 + 3][xr0] = a0.w;
        xs[xk0 + 0][xr0 + 32] = a1.x; xs[xk0 + 1][xr0 + 32] = a1.y;
        xs[xk0 + 2][xr0 + 32] = a1.z; xs[xk0 + 3][xr0 + 32] = a1.w;
        ws[wk + 0][wr] = w.x; ws[wk + 1][wr] = w.y;
        ws[wk + 2][wr] = w.z; ws[wk + 3][wr] = w.w;
        __syncthreads();
        #pragma unroll
        for (int kk = 0; kk < 32; kk++) {
            float ar[4];
            #pragma unroll
            for (int i = 0; i < 4; i++) ar[i] = xs[kk][ty * 4 + i];
            float b0 = ws[kk][tx * 2 + 0];
            float b1 = ws[kk][tx * 2 + 1];
            #pragma unroll
            for (int i = 0; i < 4; i++) {
                acc[i][0] = fmaf(ar[i], b0, acc[i][0]);
                acc[i][1] = fmaf(ar[i], b1, acc[i][1]);
            }
        }
        // write transposed x tile: g_xT[k0+kk][mbase + m]
        {
            const int kk = tid >> 3;
            const int mq = (tid & 7) * 8;
            float* dst = g_xT + (size_t)(k0 + kk) * Mrows + mbase + mq;
            ((float4*)dst)[0] = *(float4*)&xs[kk][mq];
            ((float4*)dst)[1] = *(float4*)&xs[kk][mq + 4];
        }
    }
    #pragma unroll
    for (int i = 0; i < 4; i++) {
        #pragma unroll
        for (int j = 0; j < 2; j++) {
            int col = tx * 2 + j;
            float bias = (col < 16) ? bB[col] : bC[col - 16];
            g_bc[(mbase + ty * 4 + i) * 32 + col] = acc[i][j] + bias;
        }
    }
}

// ---------------------------------------------------------------------------
// Kernel 3: scan. 16 lanes = 16 states of one channel; 2 channels per warp.
// ---------------------------------------------------------------------------
__global__ void __launch_bounds__(256) k_scan2(const float* __restrict__ logA)
{
    __shared__ float bs[2][16 * 32];
    const int tid  = threadIdx.x;
    const int lane = tid & 31;
    const int n    = lane & 15;
    const int half = lane >> 4;
    const int warp = tid >> 5;
    const int ch   = blockIdx.x * 16 + warp * 2 + half;   // 0..2047
    const int b    = ch >> 10;
    const int d    = ch & 1023;

    const float A2 = -expf(logA[d * Ns + n]) * LOG2E;

    const float4* dT = (const float4*)(g_dT + (size_t)d * Mrows + b * Lseq);
    const float4* xT = (const float4*)(g_xT + (size_t)d * Mrows + b * Lseq);
    float* yp = g_yT + (size_t)ch * Lseq;
    const float* bcsrc = g_bc + (size_t)(b * Lseq) * 32;

    bs[0][tid]       = bcsrc[tid];
    bs[0][tid + 256] = bcsrc[tid + 256];
    __syncthreads();

    float h = 0.f;
    #pragma unroll 1
    for (int l0 = 0; l0 < Lseq; l0 += 16) {
        const int p = (l0 >> 4) & 1;
        float nb0 = 0.f, nb1 = 0.f;
        const bool more = (l0 + 16 < Lseq);
        if (more) {
            nb0 = bcsrc[(l0 + 16) * 32 + tid];
            nb1 = bcsrc[(l0 + 16) * 32 + tid + 256];
        }
        float4 dv4[4], xv4[4];
        #pragma unroll
        for (int gq = 0; gq < 4; gq++) {
            dv4[gq] = dT[(l0 >> 2) + gq];
            xv4[gq] = xT[(l0 >> 2) + gq];
        }
        #pragma unroll
        for (int gq = 0; gq < 4; gq++) {
            float dvs[4] = {dv4[gq].x, dv4[gq].y, dv4[gq].z, dv4[gq].w};
            float xvs[4] = {xv4[gq].x, xv4[gq].y, xv4[gq].z, xv4[gq].w};
            float y[4];
            #pragma unroll
            for (int i = 0; i < 4; i++) {
                const int st = gq * 4 + i;
                float dA  = fast_exp2(dvs[i] * A2);
                float dBx = dvs[i] * xvs[i] * bs[p][st * 32 + n];
                h = fmaf(dA, h, dBx);
                float pr = h * bs[p][st * 32 + 16 + n];
                pr += __shfl_xor_sync(0xffffffffu, pr, 8);
                pr += __shfl_xor_sync(0xffffffffu, pr, 4);
                pr += __shfl_xor_sync(0xffffffffu, pr, 2);
                pr += __shfl_xor_sync(0xffffffffu, pr, 1);
                y[i] = pr;
            }
            if (n == 0)
                *(float4*)(yp + l0 + gq * 4) = make_float4(y[0], y[1], y[2], y[3]);
        }
        if (more) {
            bs[p ^ 1][tid]       = nb0;
            bs[p ^ 1][tid + 256] = nb1;
        }
        __syncthreads();
    }
}

// ---------------------------------------------------------------------------
// Kernel 4: finalize. out[b,l,d] = yT[ch][l] + x*Dskip, float4 both sides.
// ---------------------------------------------------------------------------
__global__ void __launch_bounds__(256) k_finalize(
        const float* __restrict__ X, const float* __restrict__ Dskip,
        float* __restrict__ out)
{
    __shared__ float t[32][33];
    const int l0 = blockIdx.x * 32;
    const int d0 = blockIdx.y * 32;
    const int b  = blockIdx.z;
    const int tid = threadIdx.x;
    {
        const int d  = tid >> 3;
        const int lq = (tid & 7) * 4;
        float4 v = *(const float4*)(g_yT + (size_t)(b * Dm + d0 + d) * Lseq + l0 + lq);
        t[lq + 0][d] = v.x; t[lq + 1][d] = v.y;
        t[lq + 2][d] = v.z; t[lq + 3][d] = v.w;
    }
    __syncthreads();
    {
        const int l  = tid >> 3;
        const int dq = (tid & 7) * 4;
        const size_t idx = (size_t)(b * Lseq + l0 + l) * Dm + d0 + dq;
        float4 xv = *(const float4*)(X + idx);
        float4 dk = *(const float4*)(Dskip + d0 + dq);
        float4 r;
        r.x = fmaf(xv.x, dk.x, t[l][dq + 0]);
        r.y = fmaf(xv.y, dk.y, t[l][dq + 1]);
        r.z = fmaf(xv.z, dk.z, t[l][dq + 2]);
        r.w = fmaf(xv.w, dk.w, t[l][dq + 3]);
        *(float4*)(out + idx) = r;
    }
}

// ---------------------------------------------------------------------------
extern "C" void kernel_launch(void* const* d_in, const int* in_sizes, int n_in,
                              void* d_out, int out_size)
{
    const float* x      = (const float*)d_in[0];
    const float* W_B    = (const float*)d_in[1];
    const float* b_B    = (const float*)d_in[2];
    const float* W_C    = (const float*)d_in[3];
    const float* b_C    = (const float*)d_in[4];
    const float* W_dt   = (const float*)d_in[5];
    const float* b_dt   = (const float*)d_in[6];
    const float* log_A  = (const float*)d_in[7];
    const float* D_skip = (const float*)d_in[8];
    float* out = (float*)d_out;

    cudaFuncSetAttribute(k_delta_mma,
        cudaFuncAttributeMaxDynamicSharedMemorySize, SMEM_GEMM);

    k_convert<<<2560, 256>>>(x, W_dt);
    dim3 g1(Dm / 128, Mrows / 128);                 // (8, 32)
    k_delta_mma<<<g1, 256, SMEM_GEMM>>>(b_dt);
    k_gemm_bc<<<Mrows / 64, 256>>>(x, W_B, b_B, W_C, b_C);
    k_scan2<<<(Bsz * Dm) / 16, 256>>>(log_A);
    dim3 g4(Lseq / 32, Dm / 32, Bsz);
    k_finalize<<<g4, 256>>>(x, D_skip, out);
}